// round 12
// baseline (speedup 1.0000x reference)
#include <cuda_runtime.h>
#include <stdint.h>

// Problem constants (fixed by the dataset)
#define T_  500
#define B_  16
#define S_  256
#define P_  128
#define L_  16

#define SEG   17     // u32 per p-list: [0]=wordCount; [1..16] packed u8 indices (64 cap)
#define STRF  9      // sl4 stride (float4s) per s
#define OST   129    // output-transpose row stride: conflict-free STS
#define PADV (-3.402823466e38f)

// Scratch (__device__ globals; allocation is forbidden). Pure fns of inputs.
__device__ unsigned short g_bitsH[L_ * P_ * 16];   // [lang][p][16] u16 membership halves
__device__ uint32_t      g_list [L_ * P_ * SEG];   // per-p packed u8 index lists

// ---------------------------------------------------------------------------
// Stage 1: membership bitmask. CTA = (lang, 16-s chunk) -> 256 CTAs x 128 thr.
// ---------------------------------------------------------------------------
__global__ __launch_bounds__(P_) void build_bits_kernel(const float* __restrict__ mats) {
    const int l  = blockIdx.x >> 4;
    const int hh = blockIdx.x & 15;
    const int p  = threadIdx.x;
    const float* base = mats + ((size_t)l * S_ + hh * 16) * P_ + p;
    uint32_t acc0 = 0, acc1 = 0;
    #pragma unroll
    for (int j = 0; j < 8; ++j) {
        float v0 = base[(size_t)(2 * j)     * P_];
        float v1 = base[(size_t)(2 * j + 1) * P_];
        acc0 |= (v0 != 0.0f ? 1u : 0u) << (2 * j);
        acc1 |= (v1 != 0.0f ? 1u : 0u) << (2 * j + 1);
    }
    g_bitsH[((l * P_ + p) << 4) + hh] = (unsigned short)(acc0 | acc1);
}

// ---------------------------------------------------------------------------
// Stage 2: warp-ballot list builder. One WARP per (lang,p): lane i owns byte i
// of the 256-bit mask; popc + shfl-scan -> write offsets; direct byte STG.
// Lists padded only to a whole u32 word (duplicate last index: idempotent
// under max). Header = true word count. No smem, no syncthreads.
// ---------------------------------------------------------------------------
__global__ __launch_bounds__(256) void build_lists_kernel() {
    const int lang = blockIdx.x >> 4;
    const int p    = ((blockIdx.x & 15) << 3) + (threadIdx.x >> 5);
    const int lane = threadIdx.x & 31;

    const uint32_t* gb = (const uint32_t*)g_bitsH + ((size_t)lang * P_ + p) * 8;
    uint32_t word = __ldg(gb + (lane >> 2));
    uint32_t byte = (word >> (8 * (lane & 3))) & 255u;
    int cnt = __popc(byte);

    int inc = cnt;                                           // inclusive scan
    #pragma unroll
    for (int d = 1; d < 32; d <<= 1) {
        int o = __shfl_up_sync(0xffffffffu, inc, d);
        if (lane >= d) inc += o;
    }
    const int total = __shfl_sync(0xffffffffu, inc, 31);
    const int base  = inc - cnt;

    int lastidx = cnt ? (lane * 8 + (31 - __clz(byte))) : -1;  // padding fill value
    #pragma unroll
    for (int d = 16; d; d >>= 1)
        lastidx = max(lastidx, __shfl_xor_sync(0xffffffffu, lastidx, d));
    const unsigned char fl = (unsigned char)max(lastidx, 0);

    unsigned char* dstb = (unsigned char*)(g_list + ((size_t)lang * P_ + p) * SEG + 1);
    uint32_t bb = byte; int off = base;
    while (bb) {                                             // <=8 iters, mostly <=2
        int j = __ffs(bb) - 1; bb &= bb - 1;
        if (off < 4 * (SEG - 1)) dstb[off] = (unsigned char)(lane * 8 + j);
        ++off;
    }

    const int realc = min(total, 4 * (SEG - 1));
    const int m = (realc + 3) >> 2;                          // true word count
    for (int o = realc + lane; o < 4 * m; o += 32) dstb[o] = fl;  // pad last word
    if (lane == 0)
        g_list[((size_t)lang * P_ + p) * SEG] = (uint32_t)m;
}

// ---------------------------------------------------------------------------
// Predicated gather step: when k >= myw, the 4 LDS.128 generate NO wavefronts
// and the 16 maxes are predicated off (accumulators untouched).
// ---------------------------------------------------------------------------
#define GATHER4(acc0, acc1, acc2, acc3, A0, A1, A2, A3, kk, mw)                 \
    asm volatile("{\n\t"                                                         \
        ".reg .pred gp;\n\t"                                                     \
        ".reg .f32 t0,t1,t2,t3,t4,t5,t6,t7,t8,t9,t10,t11,t12,t13,t14,t15;\n\t"  \
        "setp.lt.s32 gp, %4, %5;\n\t"                                            \
        "@gp ld.shared.v4.f32 {t0,t1,t2,t3}, [%6];\n\t"                          \
        "@gp ld.shared.v4.f32 {t4,t5,t6,t7}, [%7];\n\t"                          \
        "@gp ld.shared.v4.f32 {t8,t9,t10,t11}, [%8];\n\t"                        \
        "@gp ld.shared.v4.f32 {t12,t13,t14,t15}, [%9];\n\t"                      \
        "@gp max.f32 %0,%0,t0;\n\t @gp max.f32 %1,%1,t1;\n\t"                    \
        "@gp max.f32 %2,%2,t2;\n\t @gp max.f32 %3,%3,t3;\n\t"                    \
        "@gp max.f32 %0,%0,t4;\n\t @gp max.f32 %1,%1,t5;\n\t"                    \
        "@gp max.f32 %2,%2,t6;\n\t @gp max.f32 %3,%3,t7;\n\t"                    \
        "@gp max.f32 %0,%0,t8;\n\t @gp max.f32 %1,%1,t9;\n\t"                    \
        "@gp max.f32 %2,%2,t10;\n\t @gp max.f32 %3,%3,t11;\n\t"                  \
        "@gp max.f32 %0,%0,t12;\n\t @gp max.f32 %1,%1,t13;\n\t"                  \
        "@gp max.f32 %2,%2,t14;\n\t @gp max.f32 %3,%3,t15;\n\t"                  \
        "}"                                                                      \
        : "+f"(acc0), "+f"(acc1), "+f"(acc2), "+f"(acc3)                         \
        : "r"(kk), "r"(mw), "r"(A0), "r"(A1), "r"(A2), "r"(A3))

// ---------------------------------------------------------------------------
// Main: CTA = (32-t tile, b) -> 256 CTAs x 1024 threads (32 warps, all 128 p).
// Warp = p-quad (quarter q -> p = wid*4+q); lane slot tl holds 4 t's (float4).
// Per iteration: 4 LDS.128 (one per quarter's word) serve 512 updates at the
// conflict floor; per-quarter predication skips wavefronts past own count.
// ---------------------------------------------------------------------------
__global__ __launch_bounds__(1024, 2) void allophone_map_kernel(
    const float* __restrict__ logits,      // [T, B, S]
    const int*   __restrict__ lang_ids,    // [B]
    float*       __restrict__ out)         // [T, B, P]
{
    __shared__ float4   sl4[S_ * STRF];    // 36,864 B (reused as transpose buffer)
    __shared__ uint32_t slist[P_ * SEG];   //  8,704 B

    const int t0    = blockIdx.x * 32;
    const int b     = blockIdx.y;
    const int tid   = threadIdx.x;
    const int lane  = tid & 31;
    const int wid   = tid >> 5;
    const int q     = lane >> 3;           // quarter -> which p of the quad
    const int tl    = lane & 7;            // t-slot (4 t's per lane)
    const int p_loc = wid * 4 + q;

    const int lang = __ldg(lang_ids + b);

    // Copy this language's lists to smem (coalesced).
    {
        const uint32_t* src = g_list + (size_t)lang * P_ * SEG;
        for (int i = tid; i < P_ * SEG; i += 1024) slist[i] = __ldg(src + i);
    }

    // Fill tile once: 2048 items (s, t-quad), 2 per thread. 4 coalesced LDG.32
    // + one STS.128; 8 lanes x 16B = all 32 banks per quarter: conflict-free.
    const float* lb = logits + b * S_;
    #pragma unroll
    for (int i = 0; i < 2; ++i) {
        int g  = i * 1024 + tid;
        int s  = g & (S_ - 1);
        int tq = g >> 8;                   // 0..7
        int ta = t0 + 4 * tq;
        int c0 = min(ta + 0, T_ - 1);      // tail clamp (stores guarded below)
        int c1 = min(ta + 1, T_ - 1);
        int c2 = min(ta + 2, T_ - 1);
        int c3 = min(ta + 3, T_ - 1);
        float4 v;
        v.x = lb[c0 * (B_ * S_) + s];      // 32-bit offsets (max ~2M)
        v.y = lb[c1 * (B_ * S_) + s];
        v.z = lb[c2 * (B_ * S_) + s];
        v.w = lb[c3 * (B_ * S_) + s];
        sl4[s * STRF + tq] = v;
    }
    __syncthreads();

    // Gather: loop to warp-max word count; own quarter predicated by myw.
    const uint32_t* lw  = slist + p_loc * SEG + 1;
    const int       myw = (int)slist[p_loc * SEG];          // quarter-uniform
    int nwmax = myw;
    nwmax = max(nwmax, __shfl_xor_sync(0xffffffffu, nwmax, 8));
    nwmax = max(nwmax, __shfl_xor_sync(0xffffffffu, nwmax, 16));

    const unsigned sl_s = (unsigned)__cvta_generic_to_shared(sl4) + tl * 16;
    float a0 = PADV, a1 = PADV, a2 = PADV, a3 = PADV;

    for (int k = 0; k < nwmax; ++k) {
        uint32_t w = lw[k];                // in-bounds even past myw (zero/pad words)
        unsigned A0 = sl_s + ( w         & 255u) * (STRF * 16);
        unsigned A1 = sl_s + ((w >>  8)  & 255u) * (STRF * 16);
        unsigned A2 = sl_s + ((w >> 16)  & 255u) * (STRF * 16);
        unsigned A3 = sl_s + ( w >> 24          ) * (STRF * 16);
        GATHER4(a0, a1, a2, a3, A0, A1, A2, A3, k, myw);
    }
    __syncthreads();                       // all sl4 reads done before reuse

    // Transpose through reused smem: banks (4tl + c + 4wid + q) mod 32 distinct.
    float* so = (float*)sl4;               // 32*129 floats < capacity
    so[(4 * tl + 0) * OST + p_loc] = a0;
    so[(4 * tl + 1) * OST + p_loc] = a1;
    so[(4 * tl + 2) * OST + p_loc] = a2;
    so[(4 * tl + 3) * OST + p_loc] = a3;
    __syncthreads();

    // Coalesced stores (128 contiguous p per t-row), tail-guarded.
    #pragma unroll
    for (int i = 0; i < 4; ++i) {
        int g2 = i * 1024 + tid;
        int t  = g2 >> 7;
        int pc = g2 & (P_ - 1);
        int tt = t0 + t;
        if (tt < T_)
            out[(tt * B_ + b) * P_ + pc] = so[t * OST + pc];
    }
}

// ---------------------------------------------------------------------------
extern "C" void kernel_launch(void* const* d_in, const int* in_sizes, int n_in,
                              void* d_out, int out_size) {
    const float* logits = (const float*)d_in[0];   // [T,B,S] f32
    const int*   langs  = (const int*)  d_in[1];   // [B] i32
    const float* mats   = (const float*)d_in[2];   // [L,S,P] f32
    // d_in[3] (mask) is redundant: mask == (mats == 0)

    build_bits_kernel <<<L_ * 16, P_>>>(mats);     // 256 CTAs
    build_lists_kernel<<<L_ * 16, 256>>>();        // 256 CTAs, warp per (lang,p)

    dim3 grid(16, B_);                             // 256 CTAs x 1024 threads
    allophone_map_kernel<<<grid, 1024>>>(logits, langs, (float*)d_out);
}

// round 13
// speedup vs baseline: 2.8839x; 2.8839x over previous
#include <cuda_runtime.h>
#include <stdint.h>

// Problem constants (fixed by the dataset)
#define T_  500
#define B_  16
#define S_  256
#define P_  128
#define L_  16

#define SEG   17     // u32 per p-list: [0] = wordCnt | realCnt<<16; [1..16] packed u8 idx
#define STRF  9      // sl4 stride (float4s) per s: quarter-warp gathers conflict-free
#define OST   129    // output-transpose row stride
#define PADV (-3.402823466e38f)

// Scratch (__device__ globals; allocation is forbidden). Pure fns of inputs.
__device__ unsigned char g_bitsB[L_ * 32 * P_];    // [lang][byte-chunk][p] membership bytes
__device__ uint32_t      g_list [L_ * P_ * SEG];   // per-p packed u8 lists, FULLY padded
__device__ int           g_rank [L_ * P_];         // [lang][rank] -> p (sorted by count)

// ---------------------------------------------------------------------------
// Stage 1: membership bytes. CTA = (lang, 8-s chunk) -> 512 CTAs x 128 thr.
// Thread: 8 independent coalesced loads -> one byte. 2x warps vs u16 version.
// ---------------------------------------------------------------------------
__global__ __launch_bounds__(P_) void build_bits_kernel(const float* __restrict__ mats) {
    const int l  = blockIdx.x >> 5;
    const int c8 = blockIdx.x & 31;
    const int p  = threadIdx.x;
    const float* base = mats + ((size_t)l * S_ + c8 * 8) * P_ + p;
    uint32_t b0 = 0, b1 = 0;
    #pragma unroll
    for (int j = 0; j < 4; ++j) {
        float v0 = base[(size_t)(2 * j)     * P_];
        float v1 = base[(size_t)(2 * j + 1) * P_];
        b0 |= (v0 != 0.0f ? 1u : 0u) << (2 * j);
        b1 |= (v1 != 0.0f ? 1u : 0u) << (2 * j + 1);
    }
    g_bitsB[(l * 32 + c8) * P_ + p] = (unsigned char)(b0 | b1);
}

// ---------------------------------------------------------------------------
// Stage 2: warp-ballot list builder. One WARP per (lang,p): lane i owns byte i
// (s = i*8..i*8+7); popc + shfl-scan -> write offsets; all 64 index bytes are
// written every call (real indices, then duplicated-last-index padding ->
// idempotent under max; empty list pads 0, fixed by select in main kernel).
// ---------------------------------------------------------------------------
__global__ __launch_bounds__(256) void build_lists_kernel() {
    const int lang = blockIdx.x >> 4;
    const int p    = ((blockIdx.x & 15) << 3) + (threadIdx.x >> 5);
    const int lane = threadIdx.x & 31;

    uint32_t byte = g_bitsB[(lang * 32 + lane) * P_ + p];
    int cnt = __popc(byte);

    int inc = cnt;                                           // inclusive scan
    #pragma unroll
    for (int d = 1; d < 32; d <<= 1) {
        int o = __shfl_up_sync(0xffffffffu, inc, d);
        if (lane >= d) inc += o;
    }
    const int total = __shfl_sync(0xffffffffu, inc, 31);
    const int base  = inc - cnt;

    int lastidx = cnt ? (lane * 8 + (31 - __clz(byte))) : -1;
    #pragma unroll
    for (int d = 16; d; d >>= 1)
        lastidx = max(lastidx, __shfl_xor_sync(0xffffffffu, lastidx, d));
    const unsigned char fl = (unsigned char)max(lastidx, 0);

    unsigned char* dstb = (unsigned char*)(g_list + ((size_t)lang * P_ + p) * SEG + 1);
    uint32_t bb = byte; int off = base;
    while (bb) {                                             // <=8 iters, mostly <=2
        int j = __ffs(bb) - 1; bb &= bb - 1;
        if (off < 4 * (SEG - 1)) dstb[off] = (unsigned char)(lane * 8 + j);
        ++off;
    }

    const int realc = min(total, 4 * (SEG - 1));
    for (int o = realc + lane; o < 4 * (SEG - 1); o += 32) dstb[o] = fl;  // full pad
    if (lane == 0) {
        const int m = (realc + 3) >> 2;
        g_list[((size_t)lang * P_ + p) * SEG] = (uint32_t)m | ((uint32_t)realc << 16);
    }
}

// ---------------------------------------------------------------------------
// Stage 3: per-lang rank of p by word count (stable via distinct keys).
// 16 CTAs x 128 threads; O(128) smem rank loop, trivial cost.
// ---------------------------------------------------------------------------
__global__ __launch_bounds__(P_) void build_rank_kernel() {
    __shared__ int skey[P_];
    const int lang = blockIdx.x;
    const int p    = threadIdx.x;
    const int m    = (int)(g_list[((size_t)lang * P_ + p) * SEG] & 0xFFFFu);
    skey[p] = m * 256 + p;
    __syncthreads();
    const int mykey = skey[p];
    int r = 0;
    #pragma unroll 8
    for (int q = 0; q < P_; ++q) r += (skey[q] < mykey);
    g_rank[lang * P_ + r] = p;
}

// ---------------------------------------------------------------------------
// Main: CTA = (32-t tile, b) -> 256 CTAs x 1024 threads (32 warps, all 128 p).
// Warp = one RANK-quad (count-adjacent lists -> near-zero quad padding).
// Quarter q -> rank p_loc = wid*4+q; lane slot tl holds 4 t's in a float4;
// each gather iteration: 4 LDS.128 serve 512 updates at the conflict floor.
// Lists fully padded -> reading past own count is a max-idempotent no-op.
// ---------------------------------------------------------------------------
__global__ __launch_bounds__(1024, 2) void allophone_map_kernel(
    const float* __restrict__ logits,      // [T, B, S]
    const int*   __restrict__ lang_ids,    // [B]
    float*       __restrict__ out)         // [T, B, P]
{
    __shared__ float4   sl4[S_ * STRF];    // 36,864 B (reused as transpose buffer)
    __shared__ uint32_t slist[P_ * SEG];   //  8,704 B (rank-ordered)
    __shared__ int      sperm[P_];         //    512 B (rank -> real p)

    const int t0    = blockIdx.x * 32;
    const int b     = blockIdx.y;
    const int tid   = threadIdx.x;
    const int lane  = tid & 31;
    const int wid   = tid >> 5;
    const int q     = lane >> 3;           // quarter -> which rank of the quad
    const int tl    = lane & 7;            // t-slot (4 t's per lane)
    const int p_loc = wid * 4 + q;         // RANK index

    const int lang = __ldg(lang_ids + b);

    if (tid < P_) sperm[tid] = __ldg(g_rank + lang * P_ + tid);
    __syncthreads();

    // Copy lists into smem in RANK order (gmem reads L2-hot).
    {
        const uint32_t* src = g_list + (size_t)lang * P_ * SEG;
        for (int i = tid; i < P_ * SEG; i += 1024) {
            int rk = i / SEG, j = i - rk * SEG;
            slist[i] = __ldg(src + sperm[rk] * SEG + j);
        }
    }

    // Fill tile once: 2048 items (s, t-quad), 2 per thread. 4 coalesced LDG.32
    // + one STS.128; 8 lanes x 16B = all 32 banks per quarter: conflict-free.
    const float* lb = logits + b * S_;
    #pragma unroll
    for (int i = 0; i < 2; ++i) {
        int g  = i * 1024 + tid;
        int s  = g & (S_ - 1);
        int tq = g >> 8;                   // 0..7
        int ta = t0 + 4 * tq;
        int c0 = min(ta + 0, T_ - 1);      // tail clamp (stores guarded below)
        int c1 = min(ta + 1, T_ - 1);
        int c2 = min(ta + 2, T_ - 1);
        int c3 = min(ta + 3, T_ - 1);
        float4 v;
        v.x = lb[c0 * (B_ * S_) + s];
        v.y = lb[c1 * (B_ * S_) + s];
        v.z = lb[c2 * (B_ * S_) + s];
        v.w = lb[c3 * (B_ * S_) + s];
        sl4[s * STRF + tq] = v;
    }
    __syncthreads();

    // Gather: warp-uniform loop to quad-max count (~= own count after sorting).
    const uint32_t* lw  = slist + p_loc * SEG + 1;
    const uint32_t  hdr = slist[p_loc * SEG];
    const int       realc = (int)(hdr >> 16);
    int nwmax = (int)(hdr & 0xFFFFu);
    nwmax = max(nwmax, __shfl_xor_sync(0xffffffffu, nwmax, 8));
    nwmax = max(nwmax, __shfl_xor_sync(0xffffffffu, nwmax, 16));

    float a0 = PADV, a1 = PADV, a2 = PADV, a3 = PADV;
    for (int k = 0; k < nwmax; ++k) {
        uint32_t w = lw[k];                // fully padded: safe & idempotent past own count
        float4 v;
        v = sl4[(w         & 255u) * STRF + tl];
        a0 = fmaxf(a0, v.x); a1 = fmaxf(a1, v.y); a2 = fmaxf(a2, v.z); a3 = fmaxf(a3, v.w);
        v = sl4[((w >>  8) & 255u) * STRF + tl];
        a0 = fmaxf(a0, v.x); a1 = fmaxf(a1, v.y); a2 = fmaxf(a2, v.z); a3 = fmaxf(a3, v.w);
        v = sl4[((w >> 16) & 255u) * STRF + tl];
        a0 = fmaxf(a0, v.x); a1 = fmaxf(a1, v.y); a2 = fmaxf(a2, v.z); a3 = fmaxf(a3, v.w);
        v = sl4[( w >> 24        ) * STRF + tl];
        a0 = fmaxf(a0, v.x); a1 = fmaxf(a1, v.y); a2 = fmaxf(a2, v.z); a3 = fmaxf(a3, v.w);
    }
    if (realc == 0) { a0 = a1 = a2 = a3 = PADV; }   // empty-list pad was s=0
    const int realp = sperm[p_loc];
    __syncthreads();                                // all sl4 reads done before reuse

    // Transpose through reused smem (perm resolved here; few-wavefront cost).
    float* so = (float*)sl4;                        // 32*129 floats < capacity
    so[(4 * tl + 0) * OST + realp] = a0;
    so[(4 * tl + 1) * OST + realp] = a1;
    so[(4 * tl + 2) * OST + realp] = a2;
    so[(4 * tl + 3) * OST + realp] = a3;
    __syncthreads();

    // Coalesced stores (128 contiguous p per t-row), tail-guarded.
    #pragma unroll
    for (int i = 0; i < 4; ++i) {
        int g2 = i * 1024 + tid;
        int t  = g2 >> 7;
        int pc = g2 & (P_ - 1);
        int tt = t0 + t;
        if (tt < T_)
            out[(tt * B_ + b) * P_ + pc] = so[t * OST + pc];
    }
}

// ---------------------------------------------------------------------------
extern "C" void kernel_launch(void* const* d_in, const int* in_sizes, int n_in,
                              void* d_out, int out_size) {
    const float* logits = (const float*)d_in[0];   // [T,B,S] f32
    const int*   langs  = (const int*)  d_in[1];   // [B] i32
    const float* mats   = (const float*)d_in[2];   // [L,S,P] f32
    // d_in[3] (mask) is redundant: mask == (mats == 0)

    build_bits_kernel <<<L_ * 32, P_>>>(mats);     // 512 CTAs
    build_lists_kernel<<<L_ * 16, 256>>>();        // 256 CTAs, warp per (lang,p)
    build_rank_kernel <<<L_, P_>>>();              // 16 CTAs, tiny

    dim3 grid(16, B_);                             // 256 CTAs x 1024 threads
    allophone_map_kernel<<<grid, 1024>>>(logits, langs, (float*)d_out);
}